// round 8
// baseline (speedup 1.0000x reference)
#include <cuda_runtime.h>
#include <cuda_bf16.h>
#include <cstdint>

// ---------------------------------------------------------------------------
// 64-layer x 64-timestep stacked LSTM, B=128, H=64.
// 128 persistent CTAs = (layer, batch-half) in clusters of 8 consecutive layers.
// Intra-cluster layer handoff: producer epilogue st.async's h (bf16 hi/lo)
// directly into consumer's double-buffered A SMEM + tx-counting mbarrier.
// Cross-cluster edges keep the global-buffer + release-flag protocol.
// GEMM: z[64,256] = A[64,128] @ W, mma.sync m16n8k16 bf16 exact 3-term split.
// ---------------------------------------------------------------------------

#define NT 64
#define NL 64
#define MB 64
#define THREADS 256
#define LDW 136
#define A16 (16 * LDW * 2)
#define ABUF 34816  // one A buffer: AH(17408) + AL(17408)

__device__ uint32_t g_Hbuf[63 * 2 * NT * MB * 64];
__device__ unsigned int g_flags[63 * 2 * NT];
__device__ float g_pred[128 * NT];
__device__ unsigned int g_done;

// ---- SMEM byte offsets (dynamic) ----
#define OFF_WH 0
#define OFF_WL 69632
#define OFF_A 139264           // 2 buffers x ABUF = 69632
#define OFF_BIAS 208896
#define OFF_W0X 209920
#define OFF_XS 210944
#define OFF_PS 211200          // 64*17*4 = 4352
#define OFF_WD 215552          // 16384 (l==63 only)
#define SMEM_BYTES 231936

__device__ __forceinline__ uint32_t smem_u32(const void* p) {
    uint32_t a;
    asm("{ .reg .u64 t; cvta.to.shared.u64 t, %1; cvt.u32.u64 %0, t; }"
        : "=r"(a) : "l"(p));
    return a;
}
__device__ __forceinline__ uint32_t mapa_u32(uint32_t la, uint32_t rank) {
    uint32_t ra;
    asm("mapa.shared::cluster.u32 %0, %1, %2;" : "=r"(ra) : "r"(la), "r"(rank));
    return ra;
}
__device__ __forceinline__ void ldsm4(uint32_t r[4], uint32_t addr) {
    asm volatile("ldmatrix.sync.aligned.m8n8.x4.shared.b16 {%0,%1,%2,%3}, [%4];"
                 : "=r"(r[0]), "=r"(r[1]), "=r"(r[2]), "=r"(r[3]) : "r"(addr));
}
__device__ __forceinline__ void mma_bf16(float d[4], const uint32_t a[4],
                                         uint32_t b0, uint32_t b1) {
    asm volatile(
        "mma.sync.aligned.m16n8k16.row.col.f32.bf16.bf16.f32 "
        "{%0,%1,%2,%3}, {%4,%5,%6,%7}, {%8,%9}, {%0,%1,%2,%3};"
        : "+f"(d[0]), "+f"(d[1]), "+f"(d[2]), "+f"(d[3])
        : "r"(a[0]), "r"(a[1]), "r"(a[2]), "r"(a[3]), "r"(b0), "r"(b1));
}
__device__ __forceinline__ float tanh_fast(float x) {
    float y;
    asm("tanh.approx.f32 %0, %1;" : "=f"(y) : "f"(x));
    return y;
}
__device__ __forceinline__ float sig_fast(float x) {
    return fmaf(0.5f, tanh_fast(0.5f * x), 0.5f);
}

#define MBAR_INIT(a, c) \
    asm volatile("mbarrier.init.shared.b64 [%0], %1;" :: "r"(a), "r"(c) : "memory")
#define MBAR_EXPECT_TX(a, n)                                              \
    asm volatile("mbarrier.arrive.expect_tx.shared.b64 _, [%0], %1;"      \
                 :: "r"(a), "r"(n) : "memory")
#define MBAR_ARRIVE_REMOTE(ra)                                            \
    asm volatile("mbarrier.arrive.shared::cluster.b64 _, [%0];"           \
                 :: "r"(ra) : "memory")
#define ST_ASYNC32(ra, v, rmb)                                            \
    asm volatile(                                                         \
        "st.async.shared::cluster.mbarrier::complete_tx::bytes.u32 "      \
        "[%0], %1, [%2];" :: "r"(ra), "r"(v), "r"(rmb) : "memory")
__device__ __forceinline__ void mbar_wait_cl(uint32_t mbar, uint32_t parity) {
    asm volatile(
        "{ .reg .pred P;\n\t"
        "W_%=:\n\t"
        "mbarrier.try_wait.parity.acquire.cluster.shared::cta.b64 P, [%0], %1;\n\t"
        "@P bra.uni D_%=;\n\t"
        "bra.uni W_%=;\n\t"
        "D_%=: }" :: "r"(mbar), "r"(parity) : "memory");
}
#define CLUSTER_SYNC()                                                    \
    do {                                                                  \
        asm volatile("barrier.cluster.arrive.aligned;" ::: "memory");     \
        asm volatile("barrier.cluster.wait.aligned;" ::: "memory");       \
    } while (0)

__global__ void reset_kernel() {
    unsigned int i = blockIdx.x * blockDim.x + threadIdx.x;
    if (i < 63u * 2u * NT) g_flags[i] = 0u;
    if (i == 0) g_done = 0u;
}

#define DO_CHUNK(kk)                                                          \
    do {                                                                      \
        uint32_t ah0[4], ah1[4], al0[4], al1[4];                              \
        uint32_t bh[4][4], blo[4][4];                                         \
        ldsm4(ah0, aAH + (kk) * 32);                                          \
        ldsm4(ah1, aAH + A16 + (kk) * 32);                                    \
        ldsm4(al0, aAL + (kk) * 32);                                          \
        ldsm4(al1, aAL + A16 + (kk) * 32);                                    \
        ldsm4(bh[0], sWHij + (kk) * 32);                                      \
        ldsm4(bh[1], sWHij + A16 + (kk) * 32);                                \
        ldsm4(bh[2], sWHfo + (kk) * 32);                                      \
        ldsm4(bh[3], sWHfo + A16 + (kk) * 32);                                \
        ldsm4(blo[0], sWLij + (kk) * 32);                                     \
        ldsm4(blo[1], sWLij + A16 + (kk) * 32);                               \
        ldsm4(blo[2], sWLfo + (kk) * 32);                                     \
        ldsm4(blo[3], sWLfo + A16 + (kk) * 32);                               \
        _Pragma("unroll") for (int q = 0; q < 8; q++) {                       \
            int np = (q < 4) ? (q >> 1) : (2 + ((q - 4) >> 1));               \
            int hf = (q & 1) * 2;                                             \
            uint32_t b0 = bh[np][hf], b1 = bh[np][hf + 1];                    \
            uint32_t l0 = blo[np][hf], l1 = blo[np][hf + 1];                  \
            mma_bf16(acc[0][q], ah0, b0, b1);                                 \
            mma_bf16(acc[0][q], ah0, l0, l1);                                 \
            mma_bf16(acc[0][q], al0, b0, b1);                                 \
            mma_bf16(acc[1][q], ah1, b0, b1);                                 \
            mma_bf16(acc[1][q], ah1, l0, l1);                                 \
            mma_bf16(acc[1][q], al1, b0, b1);                                 \
        }                                                                     \
    } while (0)

__global__ void __launch_bounds__(THREADS, 1) __cluster_dims__(8, 1, 1)
lstm_mma_kernel(
    const float* __restrict__ x, const float* __restrict__ W0,
    const float* __restrict__ b0, const float* __restrict__ bl,
    const float* __restrict__ Wd, const float* __restrict__ bd,
    const float* __restrict__ Wl, const float* __restrict__ labels,
    float* __restrict__ out, int out_size) {
    extern __shared__ char sm[];
    __shared__ __align__(8) unsigned long long s_full[2], s_empty[2];

    const int tid = threadIdx.x, lane = tid & 31, warp = tid >> 5;
    const int bx = blockIdx.x;
    const int half = bx >> 6, l = bx & 63;
    const uint32_t rank = (uint32_t)(bx & 7);
    const int mwarp = warp >> 2, nwarp = warp & 3;
    const uint32_t smb = smem_u32(sm);

    float* bias_s = (float*)(sm + OFF_BIAS);
    float* w0x_s  = (float*)(sm + OFF_W0X);
    float* x_s    = (float*)(sm + OFF_XS);
    float* Wd_s   = (float*)(sm + OFF_WD);
    float* ps     = (float*)(sm + OFF_PS);

    // ---- init: in-place weight prep ----
    for (int i = tid; i < 32768; i += THREADS) {
        int k = i >> 8, n = i & 255;
        float w;
        if (l == 0) {
            w = (k < 64) ? 0.0f : W0[(size_t)(k - 63) * 256 + n];
        } else {
            w = Wl[((size_t)(l - 1) * 128 + k) * 256 + n];
        }
        int g = n >> 6, h = n & 63;
        int np = (g < 2) ? (h * 2 + g) : (128 + h * 2 + (g - 2));
        __nv_bfloat16 hi = __float2bfloat16(w);
        __nv_bfloat16 lo = __float2bfloat16(w - __bfloat162float(hi));
        *(unsigned short*)(sm + OFF_WH + np * (LDW * 2) + k * 2) =
            __bfloat16_as_ushort(hi);
        *(unsigned short*)(sm + OFF_WL + np * (LDW * 2) + k * 2) =
            __bfloat16_as_ushort(lo);
    }
    for (int i = tid; i < 256; i += THREADS)
        bias_s[i] = (l == 0) ? b0[i] : bl[(size_t)(l - 1) * 256 + i];
    if (l == 0)
        for (int i = tid; i < 256; i += THREADS) w0x_s[i] = W0[i];
    for (int i = tid; i < (2 * ABUF) / 4; i += THREADS)
        ((uint32_t*)(sm + OFF_A))[i] = 0u;
    if (l == NL - 1)
        for (int i = tid; i < 64 * 64; i += THREADS) Wd_s[i] = Wd[i];
    if (tid == 0) {
        MBAR_INIT(smem_u32(&s_full[0]), 1u);
        MBAR_INIT(smem_u32(&s_full[1]), 1u);
        MBAR_INIT(smem_u32(&s_empty[0]), 8u);
        MBAR_INIT(smem_u32(&s_empty[1]), 8u);
    }
    __syncthreads();
    CLUSTER_SYNC();  // all mbars live before any remote op

    // remote address precompute
    uint32_t rfull[2] = {0u, 0u}, rA[2] = {0u, 0u}, rempty[2] = {0u, 0u};
    if (rank < 7u) {
        rfull[0] = mapa_u32(smem_u32(&s_full[0]), rank + 1u);
        rfull[1] = mapa_u32(smem_u32(&s_full[1]), rank + 1u);
        rA[0] = mapa_u32(smb + OFF_A, rank + 1u);
        rA[1] = rA[0] + ABUF;
    }
    if (rank > 0u) {
        rempty[0] = mapa_u32(smem_u32(&s_empty[0]), rank - 1u);
        rempty[1] = mapa_u32(smem_u32(&s_empty[1]), rank - 1u);
    }

    // ---- lane ldmatrix bases ----
    const uint32_t aRow = ((uint32_t)((lane & 15) * LDW + (lane >> 4) * 8)) * 2u;
    const uint32_t sAHb = smb + OFF_A + aRow;
    const uint32_t bLane =
        ((uint32_t)((((lane >> 4) & 1) * 8 + (lane & 7)) * LDW +
                    ((lane >> 3) & 1) * 8)) * 2u;
    const uint32_t sWHij = smb + OFF_WH + (uint32_t)(nwarp * 32 * LDW) * 2u + bLane;
    const uint32_t sWHfo =
        smb + OFF_WH + (uint32_t)((128 + nwarp * 32) * LDW) * 2u + bLane;
    const uint32_t sWLij = sWHij + (OFF_WL - OFF_WH);
    const uint32_t sWLfo = sWHfo + (OFF_WL - OFF_WH);

    float creg[16];
#pragma unroll
    for (int i = 0; i < 16; i++) creg[i] = 0.0f;

    for (int t = 0; t < NT; ++t) {
        const int p = t & 1;
        const uint32_t aAH = sAHb + (uint32_t)p * ABUF;
        const uint32_t aAL = aAH + 17408u;

        if (rank > 0u && tid == 0)
            MBAR_EXPECT_TX(smem_u32(&s_full[p]), 16384u);

        float acc[2][8][4];
#pragma unroll
        for (int i = 0; i < 2; i++)
#pragma unroll
            for (int j = 0; j < 8; j++)
#pragma unroll
                for (int c = 0; c < 4; c++) acc[i][j][c] = 0.0f;

        // ---- [A] h_prev half (k 64..127) from buffer p ----
        DO_CHUNK(4); DO_CHUNK(5); DO_CHUNK(6); DO_CHUNK(7);

        if (l == 0) {
            if (tid < MB) x_s[tid] = x[(size_t)(half * MB + tid) * NT + t];
            __syncthreads();
        } else if (rank == 0u) {
            // cross-cluster edge: global flag + restage
            if (tid == 0) {
                const unsigned int* fp = &g_flags[((l - 1) * 2 + half) * NT + t];
                unsigned int v;
                do {
                    asm volatile("ld.acquire.gpu.global.b32 %0, [%1];"
                                 : "=r"(v) : "l"(fp));
                } while (v == 0u);
            }
            __syncthreads();
            const uint32_t* src =
                g_Hbuf + (size_t)(((l - 1) * 2 + half) * NT + t) * 4096;
            int b = tid >> 2, h0 = (tid & 3) * 16;
            uint32_t u[16];
            const uint4* s4 = (const uint4*)(src + b * 64 + h0);
#pragma unroll
            for (int j = 0; j < 4; j++) {
                uint4 v = s4[j];
                u[j * 4] = v.x; u[j * 4 + 1] = v.y;
                u[j * 4 + 2] = v.z; u[j * 4 + 3] = v.w;
            }
            char* dstA = sm + OFF_A + (size_t)p * ABUF;
#pragma unroll
            for (int j = 0; j < 16; j += 4) {
                uint2 hip, lop;
                hip.x = __byte_perm(u[j], u[j + 1], 0x5410);
                hip.y = __byte_perm(u[j + 2], u[j + 3], 0x5410);
                lop.x = __byte_perm(u[j], u[j + 1], 0x7632);
                lop.y = __byte_perm(u[j + 2], u[j + 3], 0x7632);
                *(uint2*)(dstA + b * (LDW * 2) + (h0 + j) * 2) = hip;
                *(uint2*)(dstA + 17408 + b * (LDW * 2) + (h0 + j) * 2) = lop;
            }
            __syncthreads();
            DO_CHUNK(0); DO_CHUNK(1); DO_CHUNK(2); DO_CHUNK(3);
        } else {
            // intra-cluster edge: wait tx-complete, consume, free
            mbar_wait_cl(smem_u32(&s_full[p]), (uint32_t)((t >> 1) & 1));
            DO_CHUNK(0); DO_CHUNK(1); DO_CHUNK(2); DO_CHUNK(3);
            if (lane == 0) MBAR_ARRIVE_REMOTE(rempty[p]);
        }

        // producer backpressure: consumer freed buffer p at t-2
        if (rank < 7u && t >= 2)
            mbar_wait_cl(smem_u32(&s_empty[p]), (uint32_t)(((t >> 1) + 1) & 1));

        // ---- [G] epilogue ----
        char* ownA = sm + OFF_A + (size_t)(p ^ 1) * ABUF;
        const uint32_t rAH = rA[p], rMB = rfull[p];
        uint32_t* gH = (rank == 7u && l < NL - 1)
            ? g_Hbuf + (size_t)((l * 2 + half) * NT + t) * 4096 : (uint32_t*)0;
#pragma unroll
        for (int mt = 0; mt < 2; mt++) {
#pragma unroll
            for (int rh = 0; rh < 2; rh++) {
                const int b = mwarp * 32 + mt * 16 + (lane >> 2) + rh * 8;
                float part = 0.0f;
                float xv = (l == 0) ? x_s[b] : 0.0f;
#pragma unroll
                for (int j = 0; j < 4; j++) {
                    const int h = nwarp * 16 + j * 4 + (lane & 3);
                    float zi = acc[mt][j][rh * 2]     + bias_s[h];
                    float zj = acc[mt][j][rh * 2 + 1] + bias_s[64 + h];
                    float zf = acc[mt][4 + j][rh * 2]     + bias_s[128 + h];
                    float zo = acc[mt][4 + j][rh * 2 + 1] + bias_s[192 + h];
                    if (l == 0) {
                        zi += xv * w0x_s[h];
                        zj += xv * w0x_s[64 + h];
                        zf += xv * w0x_s[128 + h];
                        zo += xv * w0x_s[192 + h];
                    }
                    const int ci = mt * 8 + rh * 4 + j;
                    float cn = fmaf(creg[ci], sig_fast(zf),
                                    sig_fast(zi) * tanh_fast(zj));
                    float h2 = tanh_fast(cn) * sig_fast(zo);
                    creg[ci] = cn;
                    unsigned short hiu =
                        __bfloat16_as_ushort(__float2bfloat16(h2));
                    float hif = __bfloat162float(__ushort_as_bfloat16(hiu));
                    unsigned short lou =
                        __bfloat16_as_ushort(__float2bfloat16(h2 - hif));
                    // own h_prev for t+1 into buffer p^1
                    *(unsigned short*)(ownA + b * (LDW * 2) + (64 + h) * 2) = hiu;
                    *(unsigned short*)(ownA + 17408 + b * (LDW * 2) +
                                       (64 + h) * 2) = lou;
                    uint32_t myw = (uint32_t)hiu | ((uint32_t)lou << 16);
                    if (rank < 7u) {
                        uint32_t otw = __shfl_xor_sync(0xffffffffu, myw, 1);
                        if (!(lane & 1)) {
                            uint32_t ahw = (myw & 0xffffu) | (otw << 16);
                            uint32_t alw = (myw >> 16) | (otw & 0xffff0000u);
                            uint32_t off =
                                (uint32_t)(b * (LDW * 2) + h * 2);
                            ST_ASYNC32(rAH + off, ahw, rMB);
                            ST_ASYNC32(rAH + 17408u + off, alw, rMB);
                        }
                    } else if (l < NL - 1) {
                        gH[b * 64 + h] = myw;
                    } else {
                        part += h2 * Wd_s[t * 64 + h];
                    }
                }
                if (l == NL - 1)
                    ps[b * 17 + nwarp * 4 + (lane & 3)] = part;
            }
        }

        // ---- [H] end of stage ----
        if (rank == 7u && l < NL - 1) {
            __syncthreads();
            if (tid == 0) {
                unsigned int one = 1u;
                asm volatile("st.release.gpu.global.b32 [%0], %1;"
                             :: "l"(&g_flags[(l * 2 + half) * NT + t]), "r"(one));
            }
        } else if (l == NL - 1) {
            __syncthreads();
            if (tid < MB) {
                const float* pp = ps + tid * 17;
                float s = bd[t];
#pragma unroll
                for (int i = 0; i < 16; i++) s += pp[i];
                g_pred[(size_t)(half * MB + tid) * NT + t] = fmaxf(s, 0.0f);
            }
        } else {
            __syncthreads();  // orders own h_prev writes vs next [A]
        }
    }

    // ---- fused finalize ----
    if (l == NL - 1) {
        __threadfence();
        __syncthreads();
        if (tid == 0) atomicAdd(&g_done, 1u);
        if (half == 0) {
            if (tid == 0) {
                unsigned int v;
                do {
                    asm volatile("ld.acquire.gpu.global.b32 %0, [%1];"
                                 : "=r"(v) : "l"(&g_done));
                } while (v < 2u);
            }
            __syncthreads();
            float s = 0.0f;
            for (int i = tid; i < 128 * NT; i += THREADS) {
                float d = labels[i] - __ldcg(&g_pred[i]);
                s += d * d;
            }
            float* red = (float*)(sm + OFF_PS);
            red[tid] = s;
            __syncthreads();
            for (int st = 128; st > 0; st >>= 1) {
                if (tid < st) red[tid] += red[tid + st];
                __syncthreads();
            }
            float loss = red[0] / (float)(128 * NT);
            if (out_size > 128 * NT) {
                for (int i = tid; i < 128 * NT; i += THREADS)
                    out[i] = __ldcg(&g_pred[i]);
                if (tid == 0)
                    for (int i = 128 * NT; i < out_size; ++i) out[i] = loss;
            } else if (out_size == 128 * NT) {
                for (int i = tid; i < 128 * NT; i += THREADS)
                    out[i] = __ldcg(&g_pred[i]);
            } else {
                for (int i = tid; i < out_size; i += THREADS) out[i] = loss;
            }
        }
    }

    CLUSTER_SYNC();  // keep peer SMEM alive until all remote ops retire
}

extern "C" void kernel_launch(void* const* d_in, const int* in_sizes, int n_in,
                              void* d_out, int out_size) {
    const float* x      = (const float*)d_in[0];
    const float* labels = (const float*)d_in[1];
    const float* W0     = (const float*)d_in[2];
    const float* b0     = (const float*)d_in[3];
    const float* Wl     = (const float*)d_in[4];
    const float* bl     = (const float*)d_in[5];
    const float* Wd     = (const float*)d_in[6];
    const float* bd     = (const float*)d_in[7];
    float* out = (float*)d_out;

    cudaFuncSetAttribute(lstm_mma_kernel,
                         cudaFuncAttributeMaxDynamicSharedMemorySize, SMEM_BYTES);

    reset_kernel<<<32, 256>>>();
    lstm_mma_kernel<<<128, THREADS, SMEM_BYTES>>>(x, W0, b0, bl, Wd, bd, Wl,
                                                  labels, out, out_size);
}

// round 9
// speedup vs baseline: 1.8392x; 1.8392x over previous
#include <cuda_runtime.h>
#include <cuda_bf16.h>
#include <cstdint>

// ---------------------------------------------------------------------------
// 64-layer x 64-timestep stacked LSTM, B=128, H=64.
// 128 persistent CTAs = (layer, batch-half), 256 threads. Global-flag pipeline.
// Single-term bf16 GEMM: z[64,256] = A[64,128] @ W, mma.sync m16n8k16.
// Gate-pair-interleaved weights -> zero-shfl epilogue; split-K before wait;
// all-thread flag poll (2 bars/stage); bf16 h handoff packed as u32 pairs.
// ---------------------------------------------------------------------------

#define NT 64
#define NL 64
#define MB 64
#define THREADS 256
#define LDW 136
#define A16 (16 * LDW * 2)

// h handoff: [l][half][t][b*32 + h/2], two adjacent-h bf16 per u32
__device__ uint32_t g_Hbuf[63 * 2 * NT * MB * 32];
__device__ unsigned int g_flags[63 * 2 * NT];
__device__ float g_pred[128 * NT];
__device__ unsigned int g_done;

// ---- SMEM byte offsets ----
#define OFF_W 0          // 256 * 272 = 69632
#define OFF_A 69632      // 64 * 272 = 17408
#define OFF_BIAS 87040   // 1024
#define OFF_W0X 88064    // 1024
#define OFF_XS 89088     // 256
#define OFF_WD 89344     // 16384
#define OFF_PS 105728    // 64*17*4 = 4352
#define SMEM_BYTES 110080

__device__ __forceinline__ uint32_t smem_u32(const void* p) {
    uint32_t a;
    asm("{ .reg .u64 t; cvta.to.shared.u64 t, %1; cvt.u32.u64 %0, t; }"
        : "=r"(a) : "l"(p));
    return a;
}
__device__ __forceinline__ void ldsm4(uint32_t r[4], uint32_t addr) {
    asm volatile("ldmatrix.sync.aligned.m8n8.x4.shared.b16 {%0,%1,%2,%3}, [%4];"
                 : "=r"(r[0]), "=r"(r[1]), "=r"(r[2]), "=r"(r[3]) : "r"(addr));
}
__device__ __forceinline__ void mma_bf16(float d[4], const uint32_t a[4],
                                         uint32_t b0, uint32_t b1) {
    asm volatile(
        "mma.sync.aligned.m16n8k16.row.col.f32.bf16.bf16.f32 "
        "{%0,%1,%2,%3}, {%4,%5,%6,%7}, {%8,%9}, {%0,%1,%2,%3};"
        : "+f"(d[0]), "+f"(d[1]), "+f"(d[2]), "+f"(d[3])
        : "r"(a[0]), "r"(a[1]), "r"(a[2]), "r"(a[3]), "r"(b0), "r"(b1));
}
__device__ __forceinline__ float tanh_fast(float x) {
    float y;
    asm("tanh.approx.f32 %0, %1;" : "=f"(y) : "f"(x));
    return y;
}
__device__ __forceinline__ float sig_fast(float x) {
    return fmaf(0.5f, tanh_fast(0.5f * x), 0.5f);
}

__global__ void reset_kernel() {
    unsigned int i = blockIdx.x * blockDim.x + threadIdx.x;
    if (i < 63u * 2u * NT) g_flags[i] = 0u;
    if (i == 0) g_done = 0u;
}

#define DO_CHUNK(kk)                                                          \
    do {                                                                      \
        uint32_t ah0[4], ah1[4], bh[4][4];                                    \
        ldsm4(ah0, sA + (kk) * 32);                                           \
        ldsm4(ah1, sA + A16 + (kk) * 32);                                     \
        ldsm4(bh[0], sWij + (kk) * 32);                                       \
        ldsm4(bh[1], sWij + A16 + (kk) * 32);                                 \
        ldsm4(bh[2], sWfo + (kk) * 32);                                       \
        ldsm4(bh[3], sWfo + A16 + (kk) * 32);                                 \
        _Pragma("unroll") for (int q = 0; q < 8; q++) {                       \
            int np = (q < 4) ? (q >> 1) : (2 + ((q - 4) >> 1));               \
            int hf = (q & 1) * 2;                                             \
            uint32_t b0 = bh[np][hf], b1 = bh[np][hf + 1];                    \
            mma_bf16(acc[0][q], ah0, b0, b1);                                 \
            mma_bf16(acc[1][q], ah1, b0, b1);                                 \
        }                                                                     \
    } while (0)

__global__ void __launch_bounds__(THREADS, 1) lstm_mma_kernel(
    const float* __restrict__ x, const float* __restrict__ W0,
    const float* __restrict__ b0, const float* __restrict__ bl,
    const float* __restrict__ Wd, const float* __restrict__ bd,
    const float* __restrict__ Wl, const float* __restrict__ labels,
    float* __restrict__ out, int out_size) {
    extern __shared__ char sm[];
    const int tid = threadIdx.x, lane = tid & 31, warp = tid >> 5;
    const int half = blockIdx.x, l = blockIdx.y;
    const int mwarp = warp >> 2, nwarp = warp & 3;
    const uint32_t smb = smem_u32(sm);

    float* bias_s = (float*)(sm + OFF_BIAS);
    float* w0x_s  = (float*)(sm + OFF_W0X);
    float* x_s    = (float*)(sm + OFF_XS);
    float* Wd_s   = (float*)(sm + OFF_WD);
    float* ps     = (float*)(sm + OFF_PS);

    // ---- init: in-place bf16 weight prep (coalesced fp32 reads) ----
    for (int i = tid; i < 32768; i += THREADS) {
        int k = i >> 8, n = i & 255;
        float w;
        if (l == 0) {
            w = (k < 64) ? 0.0f : W0[(size_t)(k - 63) * 256 + n];
        } else {
            w = Wl[((size_t)(l - 1) * 128 + k) * 256 + n];
        }
        int g = n >> 6, h = n & 63;
        int np = (g < 2) ? (h * 2 + g) : (128 + h * 2 + (g - 2));
        *(unsigned short*)(sm + OFF_W + np * (LDW * 2) + k * 2) =
            __bfloat16_as_ushort(__float2bfloat16(w));
    }
    for (int i = tid; i < 256; i += THREADS)
        bias_s[i] = (l == 0) ? b0[i] : bl[(size_t)(l - 1) * 256 + i];
    if (l == 0)
        for (int i = tid; i < 256; i += THREADS) w0x_s[i] = W0[i];
    for (int i = tid; i < 17408 / 4; i += THREADS)
        ((uint32_t*)(sm + OFF_A))[i] = 0u;
    if (l == NL - 1)
        for (int i = tid; i < 64 * 64; i += THREADS) Wd_s[i] = Wd[i];
    __syncthreads();

    // ---- lane ldmatrix bases ----
    const uint32_t aRow = ((uint32_t)((lane & 15) * LDW + (lane >> 4) * 8)) * 2u;
    const uint32_t sA = smb + OFF_A + aRow;
    const uint32_t bLane =
        ((uint32_t)((((lane >> 4) & 1) * 8 + (lane & 7)) * LDW +
                    ((lane >> 3) & 1) * 8)) * 2u;
    const uint32_t sWij = smb + OFF_W + (uint32_t)(nwarp * 32 * LDW) * 2u + bLane;
    const uint32_t sWfo =
        smb + OFF_W + (uint32_t)((128 + nwarp * 32) * LDW) * 2u + bLane;

    // restage mapping: thread -> (b row, 16 h cols)
    const int rb = tid >> 2, rq = tid & 3;

    float creg[16];
#pragma unroll
    for (int i = 0; i < 16; i++) creg[i] = 0.0f;

    for (int t = 0; t < NT; ++t) {
        float acc[2][8][4];
#pragma unroll
        for (int i = 0; i < 2; i++)
#pragma unroll
            for (int j = 0; j < 8; j++)
#pragma unroll
                for (int c = 0; c < 4; c++) acc[i][j][c] = 0.0f;

        // ---- [A] h_prev half (k 64..127) — before any wait ----
        DO_CHUNK(4); DO_CHUNK(5); DO_CHUNK(6); DO_CHUNK(7);

        if (l > 0) {
            // ---- [B] all-thread acquire poll ----
            {
                const unsigned int* fp = &g_flags[((l - 1) * 2 + half) * NT + t];
                unsigned int v;
                do {
                    asm volatile("ld.acquire.gpu.global.b32 %0, [%1];"
                                 : "=r"(v) : "l"(fp));
                } while (v == 0u);
            }
            // ---- [C] restage h_in (cols 0..63): 2x LDG.128 + 2x STS.128 ----
            const uint4* s4 = (const uint4*)(
                g_Hbuf + (size_t)(((l - 1) * 2 + half) * NT + t) * 2048 +
                rb * 32 + rq * 8);
            uint4 v0 = s4[0], v1 = s4[1];
            char* dstA = sm + OFF_A + rb * (LDW * 2) + rq * 32;
            *(uint4*)dstA = v0;
            *(uint4*)(dstA + 16) = v1;
            __syncthreads();
            // ---- [E] h_in half (k 0..63) ----
            DO_CHUNK(0); DO_CHUNK(1); DO_CHUNK(2); DO_CHUNK(3);
        } else {
            if (tid < MB) x_s[tid] = x[(size_t)(half * MB + tid) * NT + t];
            __syncthreads();
        }

        // ---- [G] epilogue: all 4 gates local, zero shfl for gates ----
        uint32_t* gH = (l < NL - 1)
            ? g_Hbuf + (size_t)((l * 2 + half) * NT + t) * 2048 : (uint32_t*)0;
#pragma unroll
        for (int mt = 0; mt < 2; mt++) {
#pragma unroll
            for (int rh = 0; rh < 2; rh++) {
                const int b = mwarp * 32 + mt * 16 + (lane >> 2) + rh * 8;
                float part = 0.0f;
                float xv = (l == 0) ? x_s[b] : 0.0f;
#pragma unroll
                for (int j = 0; j < 4; j++) {
                    const int h = nwarp * 16 + j * 4 + (lane & 3);
                    float zi = acc[mt][j][rh * 2]     + bias_s[h];
                    float zj = acc[mt][j][rh * 2 + 1] + bias_s[64 + h];
                    float zf = acc[mt][4 + j][rh * 2]     + bias_s[128 + h];
                    float zo = acc[mt][4 + j][rh * 2 + 1] + bias_s[192 + h];
                    if (l == 0) {
                        zi += xv * w0x_s[h];
                        zj += xv * w0x_s[64 + h];
                        zf += xv * w0x_s[128 + h];
                        zo += xv * w0x_s[192 + h];
                    }
                    const int ci = mt * 8 + rh * 4 + j;
                    float cn = fmaf(creg[ci], sig_fast(zf),
                                    sig_fast(zi) * tanh_fast(zj));
                    float h2 = tanh_fast(cn) * sig_fast(zo);
                    creg[ci] = cn;
                    unsigned short hiu =
                        __bfloat16_as_ushort(__float2bfloat16(h2));
                    // own h_prev for t+1 (cols 64..127)
                    *(unsigned short*)(sm + OFF_A + b * (LDW * 2) +
                                       (64 + h) * 2) = hiu;
                    if (l < NL - 1) {
                        uint32_t otw =
                            __shfl_xor_sync(0xffffffffu, (uint32_t)hiu, 1);
                        if (!(lane & 1))
                            gH[b * 32 + (h >> 1)] =
                                (uint32_t)hiu | (otw << 16);
                    } else {
                        part += h2 * Wd_s[t * 64 + h];
                    }
                }
                if (l == NL - 1)
                    ps[b * 17 + nwarp * 4 + (lane & 3)] = part;
            }
        }

        // ---- [H] publish / head ----
        if (l < NL - 1) {
            __syncthreads();
            if (tid == 0) {
                unsigned int one = 1u;
                asm volatile("st.release.gpu.global.b32 [%0], %1;"
                             :: "l"(&g_flags[(l * 2 + half) * NT + t]), "r"(one));
            }
        } else {
            __syncthreads();
            if (tid < MB) {
                const float* pp = ps + tid * 17;
                float s = bd[t];
#pragma unroll
                for (int i = 0; i < 16; i++) s += pp[i];
                g_pred[(size_t)(half * MB + tid) * NT + t] = fmaxf(s, 0.0f);
            }
        }
    }

    // ---- fused finalize ----
    if (l == NL - 1) {
        __threadfence();
        __syncthreads();
        if (tid == 0) atomicAdd(&g_done, 1u);
        if (half == 0) {
            if (tid == 0) {
                unsigned int v;
                do {
                    asm volatile("ld.acquire.gpu.global.b32 %0, [%1];"
                                 : "=r"(v) : "l"(&g_done));
                } while (v < 2u);
            }
            __syncthreads();
            float s = 0.0f;
            for (int i = tid; i < 128 * NT; i += THREADS) {
                float d = labels[i] - __ldcg(&g_pred[i]);
                s += d * d;
            }
            float* red = (float*)(sm + OFF_PS);
            red[tid] = s;
            __syncthreads();
            for (int st = 128; st > 0; st >>= 1) {
                if (tid < st) red[tid] += red[tid + st];
                __syncthreads();
            }
            float loss = red[0] / (float)(128 * NT);
            if (out_size > 128 * NT) {
                for (int i = tid; i < 128 * NT; i += THREADS)
                    out[i] = __ldcg(&g_pred[i]);
                if (tid == 0)
                    for (int i = 128 * NT; i < out_size; ++i) out[i] = loss;
            } else if (out_size == 128 * NT) {
                for (int i = tid; i < 128 * NT; i += THREADS)
                    out[i] = __ldcg(&g_pred[i]);
            } else {
                for (int i = tid; i < out_size; i += THREADS) out[i] = loss;
            }
        }
    }
}

extern "C" void kernel_launch(void* const* d_in, const int* in_sizes, int n_in,
                              void* d_out, int out_size) {
    const float* x      = (const float*)d_in[0];
    const float* labels = (const float*)d_in[1];
    const float* W0     = (const float*)d_in[2];
    const float* b0     = (const float*)d_in[3];
    const float* Wl     = (const float*)d_in[4];
    const float* bl     = (const float*)d_in[5];
    const float* Wd     = (const float*)d_in[6];
    const float* bd     = (const float*)d_in[7];
    float* out = (float*)d_out;

    cudaFuncSetAttribute(lstm_mma_kernel,
                         cudaFuncAttributeMaxDynamicSharedMemorySize, SMEM_BYTES);

    reset_kernel<<<32, 256>>>();
    dim3 grid(2, NL);
    lstm_mma_kernel<<<grid, THREADS, SMEM_BYTES>>>(x, W0, b0, bl, Wd, bd, Wl,
                                                   labels, out, out_size);
}

// round 11
// speedup vs baseline: 1.8654x; 1.0143x over previous
#include <cuda_runtime.h>
#include <cuda_bf16.h>
#include <cstdint>

// ---------------------------------------------------------------------------
// 64-layer x 64-timestep stacked LSTM, B=128, H=64.
// 128 persistent CTAs = (layer, batch-half), 256 threads. Global-flag pipeline.
// Single-term bf16 GEMM: z[64,256] = A[64,128] @ W, mma.sync m16n8k16.
// R10: mwarp A-fragment fix; W fragments for k-chunks 5-7 register-resident
// (constant across t) -> [A] self-edge has only 2 A-ldsm per reg-chunk.
// ---------------------------------------------------------------------------

#define NT 64
#define NL 64
#define MB 64
#define THREADS 256
#define LDW 136
#define A16 (16 * LDW * 2)

// h handoff: [l][half][t][b*32 + h/2], two adjacent-h bf16 per u32
__device__ uint32_t g_Hbuf[63 * 2 * NT * MB * 32];
__device__ unsigned int g_flags[63 * 2 * NT];
__device__ float g_pred[128 * NT];
__device__ unsigned int g_done;

// ---- SMEM byte offsets ----
#define OFF_W 0          // 256 * 272 = 69632
#define OFF_A 69632      // 64 * 272 = 17408
#define OFF_BIAS 87040
#define OFF_W0X 88064
#define OFF_XS 89088
#define OFF_WD 89344
#define OFF_PS 105728
#define SMEM_BYTES 110080

__device__ __forceinline__ uint32_t smem_u32(const void* p) {
    uint32_t a;
    asm("{ .reg .u64 t; cvta.to.shared.u64 t, %1; cvt.u32.u64 %0, t; }"
        : "=r"(a) : "l"(p));
    return a;
}
__device__ __forceinline__ void ldsm4(uint32_t r[4], uint32_t addr) {
    asm volatile("ldmatrix.sync.aligned.m8n8.x4.shared.b16 {%0,%1,%2,%3}, [%4];"
                 : "=r"(r[0]), "=r"(r[1]), "=r"(r[2]), "=r"(r[3]) : "r"(addr));
}
__device__ __forceinline__ void mma_bf16(float d[4], const uint32_t a[4],
                                         uint32_t b0, uint32_t b1) {
    asm volatile(
        "mma.sync.aligned.m16n8k16.row.col.f32.bf16.bf16.f32 "
        "{%0,%1,%2,%3}, {%4,%5,%6,%7}, {%8,%9}, {%0,%1,%2,%3};"
        : "+f"(d[0]), "+f"(d[1]), "+f"(d[2]), "+f"(d[3])
        : "r"(a[0]), "r"(a[1]), "r"(a[2]), "r"(a[3]), "r"(b0), "r"(b1));
}
__device__ __forceinline__ float tanh_fast(float x) {
    float y;
    asm("tanh.approx.f32 %0, %1;" : "=f"(y) : "f"(x));
    return y;
}
__device__ __forceinline__ float sig_fast(float x) {
    return fmaf(0.5f, tanh_fast(0.5f * x), 0.5f);
}

__global__ void reset_kernel() {
    unsigned int i = blockIdx.x * blockDim.x + threadIdx.x;
    if (i < 63u * 2u * NT) g_flags[i] = 0u;
    if (i == 0) g_done = 0u;
}

// SMEM-weight chunk
#define DO_CHUNK(kk)                                                          \
    do {                                                                      \
        uint32_t ah0[4], ah1[4], bh[4][4];                                    \
        ldsm4(ah0, sA + (kk) * 32);                                           \
        ldsm4(ah1, sA + A16 + (kk) * 32);                                     \
        ldsm4(bh[0], sWij + (kk) * 32);                                       \
        ldsm4(bh[1], sWij + A16 + (kk) * 32);                                 \
        ldsm4(bh[2], sWfo + (kk) * 32);                                       \
        ldsm4(bh[3], sWfo + A16 + (kk) * 32);                                 \
        _Pragma("unroll") for (int q = 0; q < 8; q++) {                       \
            int np = (q < 4) ? (q >> 1) : (2 + ((q - 4) >> 1));               \
            int hf = (q & 1) * 2;                                             \
            uint32_t b0 = bh[np][hf], b1 = bh[np][hf + 1];                    \
            mma_bf16(acc[0][q], ah0, b0, b1);                                 \
            mma_bf16(acc[1][q], ah1, b0, b1);                                 \
        }                                                                     \
    } while (0)

// register-resident-weight chunk (only 2 A-ldsm)
#define DO_CHUNK_REG(kk, wr)                                                  \
    do {                                                                      \
        uint32_t ah0[4], ah1[4];                                              \
        ldsm4(ah0, sA + (kk) * 32);                                           \
        ldsm4(ah1, sA + A16 + (kk) * 32);                                     \
        _Pragma("unroll") for (int q = 0; q < 8; q++) {                       \
            int np = (q < 4) ? (q >> 1) : (2 + ((q - 4) >> 1));               \
            int hf = (q & 1) * 2;                                             \
            uint32_t b0 = (wr)[np][hf], b1 = (wr)[np][hf + 1];                \
            mma_bf16(acc[0][q], ah0, b0, b1);                                 \
            mma_bf16(acc[1][q], ah1, b0, b1);                                 \
        }                                                                     \
    } while (0)

__global__ void __launch_bounds__(THREADS, 1) lstm_mma_kernel(
    const float* __restrict__ x, const float* __restrict__ W0,
    const float* __restrict__ b0, const float* __restrict__ bl,
    const float* __restrict__ Wd, const float* __restrict__ bd,
    const float* __restrict__ Wl, const float* __restrict__ labels,
    float* __restrict__ out, int out_size) {
    extern __shared__ char sm[];
    const int tid = threadIdx.x, lane = tid & 31, warp = tid >> 5;
    const int half = blockIdx.x, l = blockIdx.y;
    const int mwarp = warp >> 2, nwarp = warp & 3;
    const uint32_t smb = smem_u32(sm);

    float* bias_s = (float*)(sm + OFF_BIAS);
    float* w0x_s  = (float*)(sm + OFF_W0X);
    float* x_s    = (float*)(sm + OFF_XS);
    float* Wd_s   = (float*)(sm + OFF_WD);
    float* ps     = (float*)(sm + OFF_PS);

    // ---- init: in-place bf16 weight prep ----
    for (int i = tid; i < 32768; i += THREADS) {
        int k = i >> 8, n = i & 255;
        float w;
        if (l == 0) {
            w = (k < 64) ? 0.0f : W0[(size_t)(k - 63) * 256 + n];
        } else {
            w = Wl[((size_t)(l - 1) * 128 + k) * 256 + n];
        }
        int g = n >> 6, h = n & 63;
        int np = (g < 2) ? (h * 2 + g) : (128 + h * 2 + (g - 2));
        *(unsigned short*)(sm + OFF_W + np * (LDW * 2) + k * 2) =
            __bfloat16_as_ushort(__float2bfloat16(w));
    }
    for (int i = tid; i < 256; i += THREADS)
        bias_s[i] = (l == 0) ? b0[i] : bl[(size_t)(l - 1) * 256 + i];
    if (l == 0)
        for (int i = tid; i < 256; i += THREADS) w0x_s[i] = W0[i];
    for (int i = tid; i < 17408 / 4; i += THREADS)
        ((uint32_t*)(sm + OFF_A))[i] = 0u;
    if (l == NL - 1)
        for (int i = tid; i < 64 * 64; i += THREADS) Wd_s[i] = Wd[i];
    __syncthreads();

    // ---- lane ldmatrix bases (A now per-mwarp: rows mwarp*32..+31) ----
    const uint32_t aRow = ((uint32_t)((lane & 15) * LDW + (lane >> 4) * 8)) * 2u;
    const uint32_t sA =
        smb + OFF_A + (uint32_t)(mwarp * 32 * LDW) * 2u + aRow;
    const uint32_t bLane =
        ((uint32_t)((((lane >> 4) & 1) * 8 + (lane & 7)) * LDW +
                    ((lane >> 3) & 1) * 8)) * 2u;
    const uint32_t sWij = smb + OFF_W + (uint32_t)(nwarp * 32 * LDW) * 2u + bLane;
    const uint32_t sWfo =
        smb + OFF_W + (uint32_t)((128 + nwarp * 32) * LDW) * 2u + bLane;

    // ---- register-resident W fragments for k-chunks 5,6,7 ----
    uint32_t wreg[3][4][4];
#pragma unroll
    for (int c = 0; c < 3; c++) {
        ldsm4(wreg[c][0], sWij + (c + 5) * 32);
        ldsm4(wreg[c][1], sWij + A16 + (c + 5) * 32);
        ldsm4(wreg[c][2], sWfo + (c + 5) * 32);
        ldsm4(wreg[c][3], sWfo + A16 + (c + 5) * 32);
    }

    const int rb = tid >> 2, rq = tid & 3;

    float creg[16];
#pragma unroll
    for (int i = 0; i < 16; i++) creg[i] = 0.0f;

    for (int t = 0; t < NT; ++t) {
        float acc[2][8][4];
#pragma unroll
        for (int i = 0; i < 2; i++)
#pragma unroll
            for (int j = 0; j < 8; j++)
#pragma unroll
                for (int c = 0; c < 4; c++) acc[i][j][c] = 0.0f;

        // ---- [A] h_prev half (k 64..127): reg-chunks first, SMEM chunk last
        DO_CHUNK_REG(5, wreg[0]);
        DO_CHUNK_REG(6, wreg[1]);
        DO_CHUNK_REG(7, wreg[2]);
        DO_CHUNK(4);

        if (l > 0) {
            // ---- [B] all-thread acquire poll ----
            {
                const unsigned int* fp = &g_flags[((l - 1) * 2 + half) * NT + t];
                unsigned int v;
                do {
                    asm volatile("ld.acquire.gpu.global.b32 %0, [%1];"
                                 : "=r"(v) : "l"(fp));
                } while (v == 0u);
            }
            // ---- [C] restage h_in (cols 0..63) ----
            const uint4* s4 = (const uint4*)(
                g_Hbuf + (size_t)(((l - 1) * 2 + half) * NT + t) * 2048 +
                rb * 32 + rq * 8);
            uint4 v0 = s4[0], v1 = s4[1];
            char* dstA = sm + OFF_A + rb * (LDW * 2) + rq * 32;
            *(uint4*)dstA = v0;
            *(uint4*)(dstA + 16) = v1;
            __syncthreads();
            // ---- [E] h_in half (k 0..63) ----
            DO_CHUNK(0); DO_CHUNK(1); DO_CHUNK(2); DO_CHUNK(3);
        } else {
            if (tid < MB) x_s[tid] = x[(size_t)(half * MB + tid) * NT + t];
            __syncthreads();
        }

        // ---- [G] epilogue ----
        uint32_t* gH = (l < NL - 1)
            ? g_Hbuf + (size_t)((l * 2 + half) * NT + t) * 2048 : (uint32_t*)0;
#pragma unroll
        for (int mt = 0; mt < 2; mt++) {
#pragma unroll
            for (int rh = 0; rh < 2; rh++) {
                const int b = mwarp * 32 + mt * 16 + (lane >> 2) + rh * 8;
                float part = 0.0f;
                float xv = (l == 0) ? x_s[b] : 0.0f;
#pragma unroll
                for (int j = 0; j < 4; j++) {
                    const int h = nwarp * 16 + j * 4 + (lane & 3);
                    float zi = acc[mt][j][rh * 2]     + bias_s[h];
                    float zj = acc[mt][j][rh * 2 + 1] + bias_s[64 + h];
                    float zf = acc[mt][4 + j][rh * 2]     + bias_s[128 + h];
                    float zo = acc[mt][4 + j][rh * 2 + 1] + bias_s[192 + h];
                    if (l == 0) {
                        zi += xv * w0x_s[h];
                        zj += xv * w0x_s[64 + h];
                        zf += xv * w0x_s[128 + h];
                        zo += xv * w0x_s[192 + h];
                    }
                    const int ci = mt * 8 + rh * 4 + j;
                    float cn = fmaf(creg[ci], sig_fast(zf),
                                    sig_fast(zi) * tanh_fast(zj));
                    float h2 = tanh_fast(cn) * sig_fast(zo);
                    creg[ci] = cn;
                    unsigned short hiu =
                        __bfloat16_as_ushort(__float2bfloat16(h2));
                    *(unsigned short*)(sm + OFF_A + b * (LDW * 2) +
                                       (64 + h) * 2) = hiu;
                    if (l < NL - 1) {
                        uint32_t otw =
                            __shfl_xor_sync(0xffffffffu, (uint32_t)hiu, 1);
                        if (!(lane & 1))
                            gH[b * 32 + (h >> 1)] =
                                (uint32_t)hiu | (otw << 16);
                    } else {
                        part += h2 * Wd_s[t * 64 + h];
                    }
                }
                if (l == NL - 1)
                    ps[b * 17 + nwarp * 4 + (lane & 3)] = part;
            }
        }

        // ---- [H] publish / head ----
        if (l < NL - 1) {
            __syncthreads();
            if (tid == 0) {
                unsigned int one = 1u;
                asm volatile("st.release.gpu.global.b32 [%0], %1;"
                             :: "l"(&g_flags[(l * 2 + half) * NT + t]), "r"(one));
            }
        } else {
            __syncthreads();
            if (tid < MB) {
                const float* pp = ps + tid * 17;
                float s = bd[t];
#pragma unroll
                for (int i = 0; i < 16; i++) s += pp[i];
                g_pred[(size_t)(half * MB + tid) * NT + t] = fmaxf(s, 0.0f);
            }
        }
    }

    // ---- fused finalize ----
    if (l == NL - 1) {
        __threadfence();
        __syncthreads();
        if (tid == 0) atomicAdd(&g_done, 1u);
        if (half == 0) {
            if (tid == 0) {
                unsigned int v;
                do {
                    asm volatile("ld.acquire.gpu.global.b32 %0, [%1];"
                                 : "=r"(v) : "l"(&g_done));
                } while (v < 2u);
            }
            __syncthreads();
            float s = 0.0f;
            for (int i = tid; i < 128 * NT; i += THREADS) {
                float d = labels[i] - __ldcg(&g_pred[i]);
                s += d * d;
            }
            float* red = (float*)(sm + OFF_PS);
            red[tid] = s;
            __syncthreads();
            for (int st = 128; st > 0; st >>= 1) {
                if (tid < st) red[tid] += red[tid + st];
                __syncthreads();
            }
            float loss = red[0] / (float)(128 * NT);
            if (out_size > 128 * NT) {
                for (int i = tid; i < 128 * NT; i += THREADS)
                    out[i] = __ldcg(&g_pred[i]);
                if (tid == 0)
                    for (int i = 128 * NT; i < out_size; ++i) out[i] = loss;
            } else if (out_size == 128 * NT) {
                for (int i = tid; i < 128 * NT; i += THREADS)
                    out[i] = __ldcg(&g_pred[i]);
            } else {
                for (int i = tid; i < out_size; i += THREADS) out[i] = loss;
            }
        }
    }
}

extern "C" void kernel_launch(void* const* d_in, const int* in_sizes, int n_in,
                              void* d_out, int out_size) {
    const float* x      = (const float*)d_in[0];
    const float* labels = (const float*)d_in[1];
    const float* W0     = (const float*)d_in[2];
    const float* b0     = (const float*)d_in[3];
    const float* Wl     = (const float*)d_in[4];
    const float* bl     = (const float*)d_in[5];
    const float* Wd     = (const float*)d_in[6];
    const float* bd     = (const float*)d_in[7];
    float* out = (float*)d_out;

    cudaFuncSetAttribute(lstm_mma_kernel,
                         cudaFuncAttributeMaxDynamicSharedMemorySize, SMEM_BYTES);

    reset_kernel<<<32, 256>>>();
    dim3 grid(2, NL);
    lstm_mma_kernel<<<grid, THREADS, SMEM_BYTES>>>(x, W0, b0, bl, Wd, bd, Wl,
                                                   labels, out, out_size);
}

// round 12
// speedup vs baseline: 1.9596x; 1.0505x over previous
#include <cuda_runtime.h>
#include <cuda_bf16.h>
#include <cstdint>

// ---------------------------------------------------------------------------
// 64-layer x 64-timestep stacked LSTM, B=128, H=64.
// 128 persistent CTAs = (layer, batch-half), now 512 threads (16 warps).
// Each warp: one m16 batch tile x 8 n-tiles -> halves per-warp serial work,
// doubling warps/SMSP to hide dependency stalls (self-loop is latency-bound).
// Single-term bf16 GEMM z[64,256] = A[64,128] @ W, mma.sync m16n8k16.
// ---------------------------------------------------------------------------

#define NT 64
#define NL 64
#define MB 64
#define THREADS 512
#define LDW 136
#define A16 (16 * LDW * 2)

// h handoff: [l][half][t][b*32 + h/2], two adjacent-h bf16 per u32
__device__ uint32_t g_Hbuf[63 * 2 * NT * MB * 32];
__device__ unsigned int g_flags[63 * 2 * NT];
__device__ float g_pred[128 * NT];
__device__ unsigned int g_done;

// ---- SMEM byte offsets ----
#define OFF_W 0          // 256 * 272 = 69632
#define OFF_A 69632      // 64 * 272 = 17408
#define OFF_BIAS 87040
#define OFF_W0X 88064
#define OFF_XS 89088
#define OFF_WD 89344
#define OFF_PS 105728    // 64*17*4 = 4352 (also finalize red[512]=2048)
#define SMEM_BYTES 110080

__device__ __forceinline__ uint32_t smem_u32(const void* p) {
    uint32_t a;
    asm("{ .reg .u64 t; cvta.to.shared.u64 t, %1; cvt.u32.u64 %0, t; }"
        : "=r"(a) : "l"(p));
    return a;
}
__device__ __forceinline__ void ldsm4(uint32_t r[4], uint32_t addr) {
    asm volatile("ldmatrix.sync.aligned.m8n8.x4.shared.b16 {%0,%1,%2,%3}, [%4];"
                 : "=r"(r[0]), "=r"(r[1]), "=r"(r[2]), "=r"(r[3]) : "r"(addr));
}
__device__ __forceinline__ void mma_bf16(float d[4], const uint32_t a[4],
                                         uint32_t b0, uint32_t b1) {
    asm volatile(
        "mma.sync.aligned.m16n8k16.row.col.f32.bf16.bf16.f32 "
        "{%0,%1,%2,%3}, {%4,%5,%6,%7}, {%8,%9}, {%0,%1,%2,%3};"
        : "+f"(d[0]), "+f"(d[1]), "+f"(d[2]), "+f"(d[3])
        : "r"(a[0]), "r"(a[1]), "r"(a[2]), "r"(a[3]), "r"(b0), "r"(b1));
}
__device__ __forceinline__ float tanh_fast(float x) {
    float y;
    asm("tanh.approx.f32 %0, %1;" : "=f"(y) : "f"(x));
    return y;
}
__device__ __forceinline__ float sig_fast(float x) {
    return fmaf(0.5f, tanh_fast(0.5f * x), 0.5f);
}

__global__ void reset_kernel() {
    unsigned int i = blockIdx.x * blockDim.x + threadIdx.x;
    if (i < 63u * 2u * NT) g_flags[i] = 0u;
    if (i == 0) g_done = 0u;
}

// one k-chunk: 1 A-ldsm (m16 tile) + 4 W-ldsm + 8 HMMA
#define DO_CHUNK(kk)                                                          \
    do {                                                                      \
        uint32_t ah[4], bh[4][4];                                             \
        ldsm4(ah, sA + (kk) * 32);                                            \
        ldsm4(bh[0], sWij + (kk) * 32);                                       \
        ldsm4(bh[1], sWij + A16 + (kk) * 32);                                 \
        ldsm4(bh[2], sWfo + (kk) * 32);                                       \
        ldsm4(bh[3], sWfo + A16 + (kk) * 32);                                 \
        _Pragma("unroll") for (int q = 0; q < 8; q++) {                       \
            int np = (q < 4) ? (q >> 1) : (2 + ((q - 4) >> 1));               \
            int hf = (q & 1) * 2;                                             \
            mma_bf16(acc[q], ah, bh[np][hf], bh[np][hf + 1]);                 \
        }                                                                     \
    } while (0)

__global__ void __launch_bounds__(THREADS, 1) lstm_mma_kernel(
    const float* __restrict__ x, const float* __restrict__ W0,
    const float* __restrict__ b0, const float* __restrict__ bl,
    const float* __restrict__ Wd, const float* __restrict__ bd,
    const float* __restrict__ Wl, const float* __restrict__ labels,
    float* __restrict__ out, int out_size) {
    extern __shared__ char sm[];
    const int tid = threadIdx.x, lane = tid & 31, warp = tid >> 5;
    const int half = blockIdx.x, l = blockIdx.y;
    const int mwarp = warp >> 2, nwarp = warp & 3;  // m16 tile / n-quarter
    const uint32_t smb = smem_u32(sm);

    float* bias_s = (float*)(sm + OFF_BIAS);
    float* w0x_s  = (float*)(sm + OFF_W0X);
    float* x_s    = (float*)(sm + OFF_XS);
    float* Wd_s   = (float*)(sm + OFF_WD);
    float* ps     = (float*)(sm + OFF_PS);

    // ---- init: in-place bf16 weight prep ----
    for (int i = tid; i < 32768; i += THREADS) {
        int k = i >> 8, n = i & 255;
        float w;
        if (l == 0) {
            w = (k < 64) ? 0.0f : W0[(size_t)(k - 63) * 256 + n];
        } else {
            w = Wl[((size_t)(l - 1) * 128 + k) * 256 + n];
        }
        int g = n >> 6, h = n & 63;
        int np = (g < 2) ? (h * 2 + g) : (128 + h * 2 + (g - 2));
        *(unsigned short*)(sm + OFF_W + np * (LDW * 2) + k * 2) =
            __bfloat16_as_ushort(__float2bfloat16(w));
    }
    for (int i = tid; i < 256; i += THREADS)
        bias_s[i] = (l == 0) ? b0[i] : bl[(size_t)(l - 1) * 256 + i];
    if (l == 0)
        for (int i = tid; i < 256; i += THREADS) w0x_s[i] = W0[i];
    for (int i = tid; i < 17408 / 4; i += THREADS)
        ((uint32_t*)(sm + OFF_A))[i] = 0u;
    if (l == NL - 1)
        for (int i = tid; i < 64 * 64; i += THREADS) Wd_s[i] = Wd[i];
    __syncthreads();

    // ---- lane ldmatrix bases ----
    const uint32_t aRow = ((uint32_t)((lane & 15) * LDW + (lane >> 4) * 8)) * 2u;
    const uint32_t sA =
        smb + OFF_A + (uint32_t)(mwarp * 16 * LDW) * 2u + aRow;
    const uint32_t bLane =
        ((uint32_t)((((lane >> 4) & 1) * 8 + (lane & 7)) * LDW +
                    ((lane >> 3) & 1) * 8)) * 2u;
    const uint32_t sWij = smb + OFF_W + (uint32_t)(nwarp * 32 * LDW) * 2u + bLane;
    const uint32_t sWfo =
        smb + OFF_W + (uint32_t)((128 + nwarp * 32) * LDW) * 2u + bLane;

    // restage mapping: one uint4 (16B) per thread: 64 rows x 128B = 8KB
    const int rb = tid >> 3, rq = tid & 7;

    float creg[8];
#pragma unroll
    for (int i = 0; i < 8; i++) creg[i] = 0.0f;

    for (int t = 0; t < NT; ++t) {
        float acc[8][4];
#pragma unroll
        for (int j = 0; j < 8; j++)
#pragma unroll
            for (int c = 0; c < 4; c++) acc[j][c] = 0.0f;

        // ---- [A] h_prev half (k 64..127) — before any wait ----
        DO_CHUNK(4); DO_CHUNK(5); DO_CHUNK(6); DO_CHUNK(7);

        if (l > 0) {
            // ---- [B] all-thread acquire poll ----
            {
                const unsigned int* fp = &g_flags[((l - 1) * 2 + half) * NT + t];
                unsigned int v;
                do {
                    asm volatile("ld.acquire.gpu.global.b32 %0, [%1];"
                                 : "=r"(v) : "l"(fp));
                } while (v == 0u);
            }
            // ---- [C] restage h_in (cols 0..63): 1x LDG.128 + 1x STS.128 ----
            const uint4* s4 = (const uint4*)(
                g_Hbuf + (size_t)(((l - 1) * 2 + half) * NT + t) * 2048 +
                rb * 32 + rq * 4);
            uint4 v0 = s4[0];
            *(uint4*)(sm + OFF_A + rb * (LDW * 2) + rq * 16) = v0;
            __syncthreads();
            // ---- [E] h_in half (k 0..63) ----
            DO_CHUNK(0); DO_CHUNK(1); DO_CHUNK(2); DO_CHUNK(3);
        } else {
            if (tid < MB) x_s[tid] = x[(size_t)(half * MB + tid) * NT + t];
            __syncthreads();
        }

        // ---- [G] epilogue: 8 cells/thread, all 4 gates local ----
        uint32_t* gH = (l < NL - 1)
            ? g_Hbuf + (size_t)((l * 2 + half) * NT + t) * 2048 : (uint32_t*)0;
#pragma unroll
        for (int rh = 0; rh < 2; rh++) {
            const int b = mwarp * 16 + (lane >> 2) + rh * 8;
            float part = 0.0f;
            float xv = (l == 0) ? x_s[b] : 0.0f;
#pragma unroll
            for (int j = 0; j < 4; j++) {
                const int h = nwarp * 16 + j * 4 + (lane & 3);
                float zi = acc[j][rh * 2]     + bias_s[h];
                float zj = acc[j][rh * 2 + 1] + bias_s[64 + h];
                float zf = acc[4 + j][rh * 2]     + bias_s[128 + h];
                float zo = acc[4 + j][rh * 2 + 1] + bias_s[192 + h];
                if (l == 0) {
                    zi += xv * w0x_s[h];
                    zj += xv * w0x_s[64 + h];
                    zf += xv * w0x_s[128 + h];
                    zo += xv * w0x_s[192 + h];
                }
                const int ci = rh * 4 + j;
                float cn = fmaf(creg[ci], sig_fast(zf),
                                sig_fast(zi) * tanh_fast(zj));
                float h2 = tanh_fast(cn) * sig_fast(zo);
                creg[ci] = cn;
                unsigned short hiu = __bfloat16_as_ushort(__float2bfloat16(h2));
                // own h_prev for t+1 (cols 64..127)
                *(unsigned short*)(sm + OFF_A + b * (LDW * 2) + (64 + h) * 2) =
                    hiu;
                if (l < NL - 1) {
                    uint32_t otw =
                        __shfl_xor_sync(0xffffffffu, (uint32_t)hiu, 1);
                    if (!(lane & 1))
                        gH[b * 32 + (h >> 1)] = (uint32_t)hiu | (otw << 16);
                } else {
                    part += h2 * Wd_s[t * 64 + h];
                }
            }
            if (l == NL - 1)
                ps[b * 17 + nwarp * 4 + (lane & 3)] = part;
        }

        // ---- [H] publish / head ----
        if (l < NL - 1) {
            __syncthreads();
            if (tid == 0) {
                unsigned int one = 1u;
                asm volatile("st.release.gpu.global.b32 [%0], %1;"
                             :: "l"(&g_flags[(l * 2 + half) * NT + t]), "r"(one));
            }
        } else {
            __syncthreads();
            if (tid < MB) {
                const float* pp = ps + tid * 17;
                float s = bd[t];
#pragma unroll
                for (int i = 0; i < 16; i++) s += pp[i];
                g_pred[(size_t)(half * MB + tid) * NT + t] = fmaxf(s, 0.0f);
            }
        }
    }

    // ---- fused finalize ----
    if (l == NL - 1) {
        __threadfence();
        __syncthreads();
        if (tid == 0) atomicAdd(&g_done, 1u);
        if (half == 0) {
            if (tid == 0) {
                unsigned int v;
                do {
                    asm volatile("ld.acquire.gpu.global.b32 %0, [%1];"
                                 : "=r"(v) : "l"(&g_done));
                } while (v < 2u);
            }
            __syncthreads();
            float s = 0.0f;
            for (int i = tid; i < 128 * NT; i += THREADS) {
                float d = labels[i] - __ldcg(&g_pred[i]);
                s += d * d;
            }
            float* red = (float*)(sm + OFF_PS);
            red[tid] = s;
            __syncthreads();
            for (int st = 256; st > 0; st >>= 1) {
                if (tid < st) red[tid] += red[tid + st];
                __syncthreads();
            }
            float loss = red[0] / (float)(128 * NT);
            if (out_size > 128 * NT) {
                for (int i = tid; i < 128 * NT; i += THREADS)
                    out[i] = __ldcg(&g_pred[i]);
                if (tid == 0)
                    for (int i = 128 * NT; i < out_size; ++i) out[i] = loss;
            } else if (out_size == 128 * NT) {
                for (int i = tid; i < 128 * NT; i += THREADS)
                    out[i] = __ldcg(&g_pred[i]);
            } else {
                for (int i = tid; i < out_size; i += THREADS) out[i] = loss;
            }
        }
    }
}

extern "C" void kernel_launch(void* const* d_in, const int* in_sizes, int n_in,
                              void* d_out, int out_size) {
    const float* x      = (const float*)d_in[0];
    const float* labels = (const float*)d_in[1];
    const float* W0     = (const float*)d_in[2];
    const float* b0     = (const float*)d_in[3];
    const float* Wl     = (const float*)d_in[4];
    const float* bl     = (const float*)d_in[5];
    const float* Wd     = (const float*)d_in[6];
    const float* bd     = (const float*)d_in[7];
    float* out = (float*)d_out;

    cudaFuncSetAttribute(lstm_mma_kernel,
                         cudaFuncAttributeMaxDynamicSharedMemorySize, SMEM_BYTES);

    reset_kernel<<<32, 256>>>();
    dim3 grid(2, NL);
    lstm_mma_kernel<<<grid, THREADS, SMEM_BYTES>>>(x, W0, b0, bl, Wd, bd, Wl,
                                                   labels, out, out_size);
}

// round 13
// speedup vs baseline: 2.0214x; 1.0315x over previous
#include <cuda_runtime.h>
#include <cuda_bf16.h>
#include <cstdint>

// ---------------------------------------------------------------------------
// 64-layer x 64-timestep stacked LSTM, B=128, H=64.
// 128 persistent CTAs = (layer, batch-half), 512 threads (16 warps).
// R13: h handoff stored PRE-PERMUTED into mma fragment layout ->
// consumer edge = poll + 4x LDG.128 straight into A fragments (no SMEM
// restage, no barrier, no A-ldsm on the inter-layer critical path).
// Single-term bf16 GEMM z[64,256] = A[64,128] @ W, mma.sync m16n8k16.
// ---------------------------------------------------------------------------

#define NT 64
#define NL 64
#define MB 64
#define THREADS 512
#define LDW 136
#define A16 (16 * LDW * 2)

// h handoff in fragment layout: [l][half][t][mt*512 + lane*16 + chunk*4 + aidx]
__device__ uint32_t g_Hbuf[63 * 2 * NT * 2048];
__device__ unsigned int g_flags[63 * 2 * NT];
__device__ float g_pred[128 * NT];
__device__ unsigned int g_done;

// ---- SMEM byte offsets ----
#define OFF_W 0          // 256 * 272 = 69632
#define OFF_A 69632      // 64 * 272 = 17408
#define OFF_BIAS 87040
#define OFF_W0X 88064
#define OFF_XS 89088
#define OFF_WD 89344
#define OFF_PS 105728
#define SMEM_BYTES 110080

__device__ __forceinline__ uint32_t smem_u32(const void* p) {
    uint32_t a;
    asm("{ .reg .u64 t; cvta.to.shared.u64 t, %1; cvt.u32.u64 %0, t; }"
        : "=r"(a) : "l"(p));
    return a;
}
__device__ __forceinline__ void ldsm4(uint32_t r[4], uint32_t addr) {
    asm volatile("ldmatrix.sync.aligned.m8n8.x4.shared.b16 {%0,%1,%2,%3}, [%4];"
                 : "=r"(r[0]), "=r"(r[1]), "=r"(r[2]), "=r"(r[3]) : "r"(addr));
}
__device__ __forceinline__ void mma_bf16(float d[4], const uint32_t a[4],
                                         uint32_t b0, uint32_t b1) {
    asm volatile(
        "mma.sync.aligned.m16n8k16.row.col.f32.bf16.bf16.f32 "
        "{%0,%1,%2,%3}, {%4,%5,%6,%7}, {%8,%9}, {%0,%1,%2,%3};"
        : "+f"(d[0]), "+f"(d[1]), "+f"(d[2]), "+f"(d[3])
        : "r"(a[0]), "r"(a[1]), "r"(a[2]), "r"(a[3]), "r"(b0), "r"(b1));
}
__device__ __forceinline__ float tanh_fast(float x) {
    float y;
    asm("tanh.approx.f32 %0, %1;" : "=f"(y) : "f"(x));
    return y;
}
__device__ __forceinline__ float sig_fast(float x) {
    return fmaf(0.5f, tanh_fast(0.5f * x), 0.5f);
}

__global__ void reset_kernel() {
    unsigned int i = blockIdx.x * blockDim.x + threadIdx.x;
    if (i < 63u * 2u * NT) g_flags[i] = 0u;
    if (i == 0) g_done = 0u;
}

// SMEM-A chunk (self h_prev half): 1 A-ldsm + 4 W-ldsm + 8 HMMA
#define DO_CHUNK(kk)                                                          \
    do {                                                                      \
        uint32_t ah[4], bh[4][4];                                             \
        ldsm4(ah, sA + (kk) * 32);                                            \
        ldsm4(bh[0], sWij + (kk) * 32);                                       \
        ldsm4(bh[1], sWij + A16 + (kk) * 32);                                 \
        ldsm4(bh[2], sWfo + (kk) * 32);                                       \
        ldsm4(bh[3], sWfo + A16 + (kk) * 32);                                 \
        _Pragma("unroll") for (int q = 0; q < 8; q++) {                       \
            int np = (q < 4) ? (q >> 1) : (2 + ((q - 4) >> 1));               \
            int hf = (q & 1) * 2;                                             \
            mma_bf16(acc[q], ah, bh[np][hf], bh[np][hf + 1]);                 \
        }                                                                     \
    } while (0)

// fragment-direct chunk (h_in half): A regs from LDG, 4 W-ldsm + 8 HMMA
#define DO_CHUNK_FRAG(kk, fv)                                                 \
    do {                                                                      \
        uint32_t ah[4] = {(fv).x, (fv).y, (fv).z, (fv).w};                    \
        uint32_t bh[4][4];                                                    \
        ldsm4(bh[0], sWij + (kk) * 32);                                       \
        ldsm4(bh[1], sWij + A16 + (kk) * 32);                                 \
        ldsm4(bh[2], sWfo + (kk) * 32);                                       \
        ldsm4(bh[3], sWfo + A16 + (kk) * 32);                                 \
        _Pragma("unroll") for (int q = 0; q < 8; q++) {                       \
            int np = (q < 4) ? (q >> 1) : (2 + ((q - 4) >> 1));               \
            int hf = (q & 1) * 2;                                             \
            mma_bf16(acc[q], ah, bh[np][hf], bh[np][hf + 1]);                 \
        }                                                                     \
    } while (0)

__global__ void __launch_bounds__(THREADS, 1) lstm_mma_kernel(
    const float* __restrict__ x, const float* __restrict__ W0,
    const float* __restrict__ b0, const float* __restrict__ bl,
    const float* __restrict__ Wd, const float* __restrict__ bd,
    const float* __restrict__ Wl, const float* __restrict__ labels,
    float* __restrict__ out, int out_size) {
    extern __shared__ char sm[];
    const int tid = threadIdx.x, lane = tid & 31, warp = tid >> 5;
    const int half = blockIdx.x, l = blockIdx.y;
    const int mwarp = warp >> 2, nwarp = warp & 3;
    const uint32_t smb = smem_u32(sm);

    float* bias_s = (float*)(sm + OFF_BIAS);
    float* w0x_s  = (float*)(sm + OFF_W0X);
    float* x_s    = (float*)(sm + OFF_XS);
    float* Wd_s   = (float*)(sm + OFF_WD);
    float* ps     = (float*)(sm + OFF_PS);

    // ---- init: in-place bf16 weight prep ----
    for (int i = tid; i < 32768; i += THREADS) {
        int k = i >> 8, n = i & 255;
        float w;
        if (l == 0) {
            w = (k < 64) ? 0.0f : W0[(size_t)(k - 63) * 256 + n];
        } else {
            w = Wl[((size_t)(l - 1) * 128 + k) * 256 + n];
        }
        int g = n >> 6, h = n & 63;
        int np = (g < 2) ? (h * 2 + g) : (128 + h * 2 + (g - 2));
        *(unsigned short*)(sm + OFF_W + np * (LDW * 2) + k * 2) =
            __bfloat16_as_ushort(__float2bfloat16(w));
    }
    for (int i = tid; i < 256; i += THREADS)
        bias_s[i] = (l == 0) ? b0[i] : bl[(size_t)(l - 1) * 256 + i];
    if (l == 0)
        for (int i = tid; i < 256; i += THREADS) w0x_s[i] = W0[i];
    for (int i = tid; i < 17408 / 4; i += THREADS)
        ((uint32_t*)(sm + OFF_A))[i] = 0u;
    if (l == NL - 1)
        for (int i = tid; i < 64 * 64; i += THREADS) Wd_s[i] = Wd[i];
    __syncthreads();

    // ---- lane ldmatrix bases ----
    const uint32_t aRow = ((uint32_t)((lane & 15) * LDW + (lane >> 4) * 8)) * 2u;
    const uint32_t sA =
        smb + OFF_A + (uint32_t)(mwarp * 16 * LDW) * 2u + aRow;
    const uint32_t bLane =
        ((uint32_t)((((lane >> 4) & 1) * 8 + (lane & 7)) * LDW +
                    ((lane >> 3) & 1) * 8)) * 2u;
    const uint32_t sWij = smb + OFF_W + (uint32_t)(nwarp * 32 * LDW) * 2u + bLane;
    const uint32_t sWfo =
        smb + OFF_W + (uint32_t)((128 + nwarp * 32) * LDW) * 2u + bLane;

    // producer fragment-scatter base index (even lanes store pairs):
    //   mt=mwarp, lane_c=(lane>>2)*4 + ((j&1)*2 + ((lane&3)>>1)), chunk=nwarp,
    //   aidx = rh + 2*(j>>1)
    const int fragBase = mwarp * 512 + (lane >> 2) * 4 * 16 + nwarp * 4;

    float creg[8];
#pragma unroll
    for (int i = 0; i < 8; i++) creg[i] = 0.0f;

    for (int t = 0; t < NT; ++t) {
        float acc[8][4];
#pragma unroll
        for (int j = 0; j < 8; j++)
#pragma unroll
            for (int c = 0; c < 4; c++) acc[j][c] = 0.0f;

        // ---- [A] h_prev half (k 64..127) — before any wait ----
        DO_CHUNK(4); DO_CHUNK(5); DO_CHUNK(6); DO_CHUNK(7);

        if (l > 0) {
            // ---- [B] all-thread acquire poll ----
            {
                const unsigned int* fp = &g_flags[((l - 1) * 2 + half) * NT + t];
                unsigned int v;
                do {
                    asm volatile("ld.acquire.gpu.global.b32 %0, [%1];"
                                 : "=r"(v) : "l"(fp));
                } while (v == 0u);
            }
            // ---- [E'] direct fragment LDG (coalesced 4x LDG.128) + MMA ----
            const uint4* fb = (const uint4*)(
                g_Hbuf + (size_t)(((l - 1) * 2 + half) * NT + t) * 2048 +
                mwarp * 512 + lane * 16);
            uint4 f0 = fb[0], f1 = fb[1], f2 = fb[2], f3 = fb[3];
            DO_CHUNK_FRAG(0, f0);
            DO_CHUNK_FRAG(1, f1);
            DO_CHUNK_FRAG(2, f2);
            DO_CHUNK_FRAG(3, f3);
        } else {
            if (tid < MB) x_s[tid] = x[(size_t)(half * MB + tid) * NT + t];
            __syncthreads();
        }

        // ---- [G] epilogue: 8 cells/thread, all 4 gates local ----
        uint32_t* gH = (l < NL - 1)
            ? g_Hbuf + (size_t)((l * 2 + half) * NT + t) * 2048 : (uint32_t*)0;
#pragma unroll
        for (int rh = 0; rh < 2; rh++) {
            const int b = mwarp * 16 + (lane >> 2) + rh * 8;
            float part = 0.0f;
            float xv = (l == 0) ? x_s[b] : 0.0f;
#pragma unroll
            for (int j = 0; j < 4; j++) {
                const int h = nwarp * 16 + j * 4 + (lane & 3);
                float zi = acc[j][rh * 2]     + bias_s[h];
                float zj = acc[j][rh * 2 + 1] + bias_s[64 + h];
                float zf = acc[4 + j][rh * 2]     + bias_s[128 + h];
                float zo = acc[4 + j][rh * 2 + 1] + bias_s[192 + h];
                if (l == 0) {
                    zi += xv * w0x_s[h];
                    zj += xv * w0x_s[64 + h];
                    zf += xv * w0x_s[128 + h];
                    zo += xv * w0x_s[192 + h];
                }
                const int ci = rh * 4 + j;
                float cn = fmaf(creg[ci], sig_fast(zf),
                                sig_fast(zi) * tanh_fast(zj));
                float h2 = tanh_fast(cn) * sig_fast(zo);
                creg[ci] = cn;
                unsigned short hiu = __bfloat16_as_ushort(__float2bfloat16(h2));
                // own h_prev for t+1 (SMEM cols 64..127)
                *(unsigned short*)(sm + OFF_A + b * (LDW * 2) + (64 + h) * 2) =
                    hiu;
                if (l < NL - 1) {
                    uint32_t otw =
                        __shfl_xor_sync(0xffffffffu, (uint32_t)hiu, 1);
                    if (!(lane & 1)) {
                        // fragment-layout scatter: pair (h, h+1)
                        int idx = fragBase +
                                  ((j & 1) * 2 + ((lane & 3) >> 1)) * 16 +
                                  rh + 2 * (j >> 1);
                        gH[idx] = (uint32_t)hiu | (otw << 16);
                    }
                } else {
                    part += h2 * Wd_s[t * 64 + h];
                }
            }
            if (l == NL - 1)
                ps[b * 17 + nwarp * 4 + (lane & 3)] = part;
        }

        // ---- [H] publish / head ----
        if (l < NL - 1) {
            __syncthreads();
            if (tid == 0) {
                unsigned int one = 1u;
                asm volatile("st.release.gpu.global.b32 [%0], %1;"
                             :: "l"(&g_flags[(l * 2 + half) * NT + t]), "r"(one));
            }
        } else {
            __syncthreads();
            if (tid < MB) {
                const float* pp = ps + tid * 17;
                float s = bd[t];
#pragma unroll
                for (int i = 0; i < 16; i++) s += pp[i];
                g_pred[(size_t)(half * MB + tid) * NT + t] = fmaxf(s, 0.0f);
            }
        }
    }

    // ---- fused finalize ----
    if (l == NL - 1) {
        __threadfence();
        __syncthreads();
        if (tid == 0) atomicAdd(&g_done, 1u);
        if (half == 0) {
            if (tid == 0) {
                unsigned int v;
                do {
                    asm volatile("ld.acquire.gpu.global.b32 %0, [%1];"
                                 : "=r"(v) : "l"(&g_done));
                } while (v < 2u);
            }
            __syncthreads();
            float s = 0.0f;
            for (int i = tid; i < 128 * NT; i += THREADS) {
                float d = labels[i] - __ldcg(&g_pred[i]);
                s += d * d;
            }
            float* red = (float*)(sm + OFF_PS);
            red[tid] = s;
            __syncthreads();
            for (int st = 256; st > 0; st >>= 1) {
                if (tid < st) red[tid] += red[tid + st];
                __syncthreads();
            }
            float loss = red[0] / (float)(128 * NT);
            if (out_size > 128 * NT) {
                for (int i = tid; i < 128 * NT; i += THREADS)
                    out[i] = __ldcg(&g_pred[i]);
                if (tid == 0)
                    for (int i = 128 * NT; i < out_size; ++i) out[i] = loss;
            } else if (out_size == 128 * NT) {
                for (int i = tid; i < 128 * NT; i += THREADS)
                    out[i] = __ldcg(&g_pred[i]);
            } else {
                for (int i = tid; i < out_size; i += THREADS) out[i] = loss;
            }
        }
    }
}

extern "C" void kernel_launch(void* const* d_in, const int* in_sizes, int n_in,
                              void* d_out, int out_size) {
    const float* x      = (const float*)d_in[0];
    const float* labels = (const float*)d_in[1];
    const float* W0     = (const float*)d_in[2];
    const float* b0     = (const float*)d_in[3];
    const float* Wl     = (const float*)d_in[4];
    const float* bl     = (const float*)d_in[5];
    const float* Wd     = (const float*)d_in[6];
    const float* bd     = (const float*)d_in[7];
    float* out = (float*)d_out;

    cudaFuncSetAttribute(lstm_mma_kernel,
                         cudaFuncAttributeMaxDynamicSharedMemorySize, SMEM_BYTES);

    reset_kernel<<<32, 256>>>();
    dim3 grid(2, NL);
    lstm_mma_kernel<<<grid, THREADS, SMEM_BYTES>>>(x, W0, b0, bl, Wd, bd, Wl,
                                                   labels, out, out_size);
}